// round 15
// baseline (speedup 1.0000x reference)
#include <cuda_runtime.h>
#include <math.h>
#include <stdint.h>

// Problem constants
#define B 16
#define S 2048
#define M 4
#define E 128
#define HH 128
#define VOCAB 100000
#define NE 4000
#define NR 200
#define FULLMASK 0xffffffffu

// mega-kernel geometry
#define GB 512            // gather blocks (barrier participants)
#define BPB 32            // gather blocks per batch (== warp size for stats combine)
#define SPB 64            // slots per gather block
#define SPW 8             // slots per warp
#define HEADW (2 + NE + NR)               // 4202 head warps
#define HB ((HEADW * 32 + 255) / 256)     // 526 head blocks
#define AB 48                             // argmax blocks
#define GRID (GB + HB + AB)               // 1086

// counter rounds: 0=h-ready(target 1), 1=stats0, 2=u1, 3=stats1, 4=u2
#define NCNT 5

// ---------------- device scratch (no allocation allowed) ----------------
__device__ float  g_h[B * HH];          // h per batch (overwritten each replay)
__device__ float  g_du[B * HH];         // u - h accumulator (zero at launch start)
__device__ float2 g_stats[2][B * BPB];  // per-block softmax partials (m, sum)
__device__ int    g_cnt[NCNT * B];      // per-batch barrier counters (monotonic in-launch)
__device__ int    g_headcnt;            // head-block completion counter
__device__ int    g_alldone;            // global completion counter (reset trigger)

// ---------------- threefry2x32-20 (JAX) ----------------
__host__ __device__ __forceinline__ uint32_t rotl32(uint32_t v, int d) {
    return (v << d) | (v >> (32 - d));
}

__host__ __device__ __forceinline__ void threefry2x32(
    uint32_t k0, uint32_t k1, uint32_t x0, uint32_t x1,
    uint32_t& o0, uint32_t& o1)
{
    uint32_t ks0 = k0, ks1 = k1;
    uint32_t ks2 = k0 ^ k1 ^ 0x1BD11BDAu;
    x0 += ks0; x1 += ks1;
    const int rA[4] = {13, 15, 26, 6};
    const int rB[4] = {17, 29, 16, 24};
    #pragma unroll
    for (int i = 0; i < 4; i++) { x0 += x1; x1 = rotl32(x1, rA[i]); x1 ^= x0; }
    x0 += ks1; x1 += ks2 + 1u;
    #pragma unroll
    for (int i = 0; i < 4; i++) { x0 += x1; x1 = rotl32(x1, rB[i]); x1 ^= x0; }
    x0 += ks2; x1 += ks0 + 2u;
    #pragma unroll
    for (int i = 0; i < 4; i++) { x0 += x1; x1 = rotl32(x1, rA[i]); x1 ^= x0; }
    x0 += ks0; x1 += ks1 + 3u;
    #pragma unroll
    for (int i = 0; i < 4; i++) { x0 += x1; x1 = rotl32(x1, rB[i]); x1 ^= x0; }
    x0 += ks1; x1 += ks2 + 4u;
    #pragma unroll
    for (int i = 0; i < 4; i++) { x0 += x1; x1 = rotl32(x1, rA[i]); x1 ^= x0; }
    x0 += ks2; x1 += ks0 + 5u;
    o0 = x0; o1 = x1;
}

// butterfly-combine 32 per-block (m, sum) partials -> (m, 1/sum), all lanes
__device__ __forceinline__ void combine_stats(const float2* st_base,
                                              int lane, float& m, float& inv)
{
    float2 st = __ldcg(st_base + lane);
    float mm = st.x;
    #pragma unroll
    for (int o = 16; o; o >>= 1) mm = fmaxf(mm, __shfl_xor_sync(FULLMASK, mm, o));
    float ss = st.y * expf(st.x - mm);
    #pragma unroll
    for (int o = 16; o; o >>= 1) ss += __shfl_xor_sync(FULLMASK, ss, o);
    m = mm; inv = 1.0f / ss;
}

// race-free end-of-launch reset: the globally LAST block to finish resets all
// persistent state. Every other block has completed all its reads before
// arriving, so no consumer can observe the reset mid-launch.
__device__ __forceinline__ void final_reset(int t)
{
    __threadfence();
    __syncthreads();
    __shared__ int s_last;
    if (t == 0) s_last = (atomicAdd(&g_alldone, 1) == GRID - 1) ? 1 : 0;
    __syncthreads();
    if (s_last) {
        for (int i = t; i < B * HH; i += 256) g_du[i] = 0.0f;
        if (t < NCNT * B) g_cnt[t] = 0;
        if (t == 0) { g_headcnt = 0; g_alldone = 0; }
    }
}

// ================================ MEGA KERNEL ================================
__global__ void __launch_bounds__(256, 5)
k_mega(const int* __restrict__ story,
       const float* __restrict__ C,
       const int* __restrict__ lengths,
       const float* __restrict__ hidden,
       const float* __restrict__ Wm, const float* __restrict__ Wb,
       const float* __restrict__ W1w, const float* __restrict__ W1b,
       const float* __restrict__ W3w, const float* __restrict__ W3b,
       const float* __restrict__ W4w, const float* __restrict__ W4b,
       float* __restrict__ o_sp, float* __restrict__ o_qh, float* __restrict__ o_qt,
       float* __restrict__ a_sp, float* __restrict__ a_qh, float* __restrict__ a_qt,
       float* __restrict__ o_mask,
       uint32_t k1a, uint32_t k1b, uint32_t k2a, uint32_t k2b,
       uint32_t k3a, uint32_t k3b)
{
    extern __shared__ float s_emb[];     // SPB x E floats = 32KB (argmax: scratch)
    __shared__ float s_logit[SPB];       // 256B
    __shared__ int4  s_idx[SPB];         // 1KB: story indices, loaded once
    __shared__ float sred[8][128];       // 4KB: cross-warp u reduce

    const size_t TBL = (size_t)VOCAB * E;
    int bid = blockIdx.x;
    int t = threadIdx.x, lane = t & 31, w = t >> 5;

    // ---------------- head-GEMV blocks ----------------
    if (bid >= GB && bid < GB + HB) {
        // wait for all 16 batches' h (counters monotonic for the whole launch)
        if (t == 0) {
            for (int b = 0; b < B; b++)
                while (atomicAdd(&g_cnt[b], 0) < 1) { }
        }
        __syncthreads();
        int gid = (bid - GB) * 256 + t;
        int hw  = gid >> 5;
        if (hw < HEADW) {
            const float *W, *bias; float* outl; int N, n;
            if (hw < 2)           { W = W1w; bias = W1b; outl = o_sp; N = 2;  n = hw; }
            else if (hw < 2 + NE) { W = W3w; bias = W3b; outl = o_qh; N = NE; n = hw - 2; }
            else                  { W = W4w; bias = W4b; outl = o_qt; N = NR; n = hw - 2 - NE; }
            float4 w4 = __ldg((const float4*)(W + (size_t)n * HH) + lane);
            float  bs = __ldg(bias + n);
            #pragma unroll
            for (int b = 0; b < B; b++) {
                float4 h4 = __ldcg((const float4*)(g_h + b * HH) + lane); // same-kernel data
                float s = w4.x * h4.x + w4.y * h4.y + w4.z * h4.z + w4.w * h4.w;
                #pragma unroll
                for (int o = 16; o; o >>= 1) s += __shfl_down_sync(FULLMASK, s, o);
                if (lane == 0) outl[b * N + n] = s + bs;
            }
        }
        __threadfence();
        __syncthreads();
        if (t == 0) atomicAdd(&g_headcnt, 1);
        final_reset(t);
        return;
    }

    // ---------------- argmax blocks (spin on head completion) ----------------
    if (bid >= GB + HB) {
        if (t == 0) { while (atomicAdd(&g_headcnt, 0) < HB) { } }
        __syncthreads();
        int blk2 = bid - GB - HB;
        int head = blk2 >> 4, b = blk2 & 15;
        const float* L; float* A; int N; uint32_t ka, kb;
        if (head == 0)      { L = o_sp; A = a_sp; N = 2;  ka = k1a; kb = k1b; }
        else if (head == 1) { L = o_qh; A = a_qh; N = NE; ka = k2a; kb = k2b; }
        else                { L = o_qt; A = a_qt; N = NR; ka = k3a; kb = k3b; }

        float bv = -INFINITY; int bi = 0x7fffffff;
        for (int i = t; i < N; i += 256) {
            int idx = b * N + i;
            float logit = __ldcg(L + idx);
            uint32_t o0, o1;
            threefry2x32(ka, kb, 0u, (uint32_t)idx, o0, o1);
            uint32_t bits = o0 ^ o1;
            float u = __uint_as_float((bits >> 9) | 0x3F800000u) - 1.0f;
            float v = fmaxf(1e-10f, u + 1e-10f);
            float g = -logf(-logf(v));
            float nv = logit + g;
            if (nv > bv || (nv == bv && i < bi)) { bv = nv; bi = i; }
        }
        float* sv = s_emb;                 // carve scratch from dynamic smem
        int*   si = (int*)(s_emb + 256);
        sv[t] = bv; si[t] = bi;
        __syncthreads();
        for (int o = 128; o; o >>= 1) {
            if (t < o) {
                if (sv[t + o] > sv[t] || (sv[t + o] == sv[t] && si[t + o] < si[t])) {
                    sv[t] = sv[t + o]; si[t] = si[t + o];
                }
            }
            __syncthreads();
        }
        int best = si[0];
        float* out = A + b * N;
        for (int i = t; i < N; i += 256) out[i] = (i == best) ? 1.0f : 0.0f;
        final_reset(t);
        return;
    }

    // ======================= gather blocks: full hop chain =======================
    int b     = bid / BPB;
    int blkin = bid % BPB;
    int slot0 = blkin * SPB;
    int lbase = w * SPW;

    // load this block's 64 story int4s once; reused by all 3 hops
    if (t < SPB) s_idx[t] = __ldg((const int4*)story + b * S + slot0 + t);

    // blkin==0 of each batch computes h[b] = Wm @ hidden_b + Wb and publishes it
    if (blkin == 0) {
        if (t < HH) {
            const float4* wr = (const float4*)(Wm + (size_t)t * HH);
            const float4* hv = (const float4*)(hidden + b * HH);
            float a = __ldg(Wb + t);
            #pragma unroll 8
            for (int k = 0; k < HH / 4; k++) {
                float4 wv = __ldg(wr + k), h4v = __ldg(hv + k);
                a += wv.x * h4v.x + wv.y * h4v.y + wv.z * h4v.z + wv.w * h4v.w;
            }
            g_h[b * HH + t] = a;
        }
        __threadfence();
        __syncthreads();
        if (t == 0) atomicAdd(&g_cnt[b], 1);   // h-ready, target 1
    }
    __syncthreads();   // s_idx visible to all warps

    // ---- hop 0: gather C0 -> s_emb (unweighted; overlaps the h computation) ----
    {
        #pragma unroll 1
        for (int i = 0; i < SPW; i += 2) {
            int4 i0 = s_idx[lbase + i];
            int4 i1 = s_idx[lbase + i + 1];
            float4 a0 = __ldg((const float4*)(C + (size_t)i0.x * E) + lane);
            float4 a1 = __ldg((const float4*)(C + (size_t)i0.y * E) + lane);
            float4 a2 = __ldg((const float4*)(C + (size_t)i0.z * E) + lane);
            float4 a3 = __ldg((const float4*)(C + (size_t)i0.w * E) + lane);
            float4 c0 = __ldg((const float4*)(C + (size_t)i1.x * E) + lane);
            float4 c1 = __ldg((const float4*)(C + (size_t)i1.y * E) + lane);
            float4 c2 = __ldg((const float4*)(C + (size_t)i1.z * E) + lane);
            float4 c3 = __ldg((const float4*)(C + (size_t)i1.w * E) + lane);
            float4 v0 = make_float4(a0.x + a1.x + a2.x + a3.x, a0.y + a1.y + a2.y + a3.y,
                                    a0.z + a1.z + a2.z + a3.z, a0.w + a1.w + a2.w + a3.w);
            float4 v1 = make_float4(c0.x + c1.x + c2.x + c3.x, c0.y + c1.y + c2.y + c3.y,
                                    c0.z + c1.z + c2.z + c3.z, c0.w + c1.w + c2.w + c3.w);
            *((float4*)&s_emb[(lbase + i) * E] + lane)     = v0;
            *((float4*)&s_emb[(lbase + i + 1) * E] + lane) = v1;
        }
    }

    // wait for h (long since published), read it into registers (kept all kernel)
    if (t == 0) { while (atomicAdd(&g_cnt[b], 0) < 1) { } }
    __syncthreads();
    float4 h4 = __ldcg((const float4*)(g_h + b * HH) + lane);

    // logits0 = emb0 . h  (smem dot)
    #pragma unroll 1
    for (int i = 0; i < SPW; i++) {
        float4 e = *((const float4*)&s_emb[(lbase + i) * E] + lane);
        float d = e.x * h4.x + e.y * h4.y + e.z * h4.z + e.w * h4.w;
        #pragma unroll
        for (int o = 16; o; o >>= 1) d += __shfl_down_sync(FULLMASK, d, o);
        if (lane == 0) s_logit[lbase + i] = d;
    }
    __syncthreads();
    // stats0 partial (warp 0), ARRIVE ONLY (no spin yet)
    if (w == 0) {
        float v0 = s_logit[lane], v1 = s_logit[lane + 32];
        float mb = fmaxf(v0, v1);
        #pragma unroll
        for (int o = 16; o; o >>= 1) mb = fmaxf(mb, __shfl_xor_sync(FULLMASK, mb, o));
        float sb = expf(v0 - mb) + expf(v1 - mb);
        #pragma unroll
        for (int o = 16; o; o >>= 1) sb += __shfl_xor_sync(FULLMASK, sb, o);
        if (lane == 0) {
            g_stats[0][b * BPB + blkin] = make_float2(mb, sb);
            __threadfence();
            atomicAdd(&g_cnt[1 * B + b], 1);
        }
    }

    // ---- gather C1 -> s_emb (overwrites emb0; overlaps the stats0 barrier) ----
    {
        const float* Ct = C + TBL;
        #pragma unroll 1
        for (int i = 0; i < SPW; i += 2) {
            int4 i0 = s_idx[lbase + i];
            int4 i1 = s_idx[lbase + i + 1];
            float4 a0 = __ldg((const float4*)(Ct + (size_t)i0.x * E) + lane);
            float4 a1 = __ldg((const float4*)(Ct + (size_t)i0.y * E) + lane);
            float4 a2 = __ldg((const float4*)(Ct + (size_t)i0.z * E) + lane);
            float4 a3 = __ldg((const float4*)(Ct + (size_t)i0.w * E) + lane);
            float4 c0 = __ldg((const float4*)(Ct + (size_t)i1.x * E) + lane);
            float4 c1 = __ldg((const float4*)(Ct + (size_t)i1.y * E) + lane);
            float4 c2 = __ldg((const float4*)(Ct + (size_t)i1.z * E) + lane);
            float4 c3 = __ldg((const float4*)(Ct + (size_t)i1.w * E) + lane);
            float4 v0 = make_float4(a0.x + a1.x + a2.x + a3.x, a0.y + a1.y + a2.y + a3.y,
                                    a0.z + a1.z + a2.z + a3.z, a0.w + a1.w + a2.w + a3.w);
            float4 v1 = make_float4(c0.x + c1.x + c2.x + c3.x, c0.y + c1.y + c2.y + c3.y,
                                    c0.z + c1.z + c2.z + c3.z, c0.w + c1.w + c2.w + c3.w);
            *((float4*)&s_emb[(lbase + i) * E] + lane)     = v0;
            *((float4*)&s_emb[(lbase + i + 1) * E] + lane) = v1;
        }
    }

    // wait for stats0, combine, weighted accumulate into g_du
    if (t == 0) { while (atomicAdd(&g_cnt[1 * B + b], 0) < BPB) { } }
    __syncthreads();
    float m0, inv0;
    combine_stats(&g_stats[0][b * BPB], lane, m0, inv0);
    {
        float4 acc = make_float4(0.f, 0.f, 0.f, 0.f);
        #pragma unroll
        for (int i = 0; i < SPW; i++) {
            float p = expf(s_logit[lbase + i] - m0) * inv0;
            float4 e = *((const float4*)&s_emb[(lbase + i) * E] + lane);
            acc.x = fmaf(p, e.x, acc.x); acc.y = fmaf(p, e.y, acc.y);
            acc.z = fmaf(p, e.z, acc.z); acc.w = fmaf(p, e.w, acc.w);
        }
        *((float4*)&sred[w][lane * 4]) = acc;
        __syncthreads();
        if (t < 128) {
            float v = sred[0][t];
            #pragma unroll
            for (int ww = 1; ww < 8; ww++) v += sred[ww][t];
            atomicAdd(&g_du[b * HH + t], v);
        }
    }
    __threadfence(); __syncthreads();
    if (t == 0) { atomicAdd(&g_cnt[2 * B + b], 1); while (atomicAdd(&g_cnt[2 * B + b], 0) < BPB) { } }
    __syncthreads();

    // ---- logits1 = emb1 . (h + du) -> s_logit ----
    {
        float4 du = __ldcg((const float4*)(g_du + b * HH) + lane);
        float4 u4 = make_float4(h4.x + du.x, h4.y + du.y, h4.z + du.z, h4.w + du.w);
        #pragma unroll 1
        for (int i = 0; i < SPW; i++) {
            float4 e = *((const float4*)&s_emb[(lbase + i) * E] + lane);
            float d = e.x * u4.x + e.y * u4.y + e.z * u4.z + e.w * u4.w;
            #pragma unroll
            for (int o = 16; o; o >>= 1) d += __shfl_down_sync(FULLMASK, d, o);
            if (lane == 0) s_logit[lbase + i] = d;
        }
    }
    __syncthreads();
    // stats1 partial + arrive only
    if (w == 0) {
        float v0 = s_logit[lane], v1 = s_logit[lane + 32];
        float mb = fmaxf(v0, v1);
        #pragma unroll
        for (int o = 16; o; o >>= 1) mb = fmaxf(mb, __shfl_xor_sync(FULLMASK, mb, o));
        float sb = expf(v0 - mb) + expf(v1 - mb);
        #pragma unroll
        for (int o = 16; o; o >>= 1) sb += __shfl_xor_sync(FULLMASK, sb, o);
        if (lane == 0) {
            g_stats[1][b * BPB + blkin] = make_float2(mb, sb);
            __threadfence();
            atomicAdd(&g_cnt[3 * B + b], 1);
        }
    }

    // ---- gather C2 -> s_emb (emb1 dead; overlaps the stats1 barrier) ----
    {
        const float* Ct = C + 2 * TBL;
        #pragma unroll 1
        for (int i = 0; i < SPW; i += 2) {
            int4 i0 = s_idx[lbase + i];
            int4 i1 = s_idx[lbase + i + 1];
            float4 a0 = __ldg((const float4*)(Ct + (size_t)i0.x * E) + lane);
            float4 a1 = __ldg((const float4*)(Ct + (size_t)i0.y * E) + lane);
            float4 a2 = __ldg((const float4*)(Ct + (size_t)i0.z * E) + lane);
            float4 a3 = __ldg((const float4*)(Ct + (size_t)i0.w * E) + lane);
            float4 c0 = __ldg((const float4*)(Ct + (size_t)i1.x * E) + lane);
            float4 c1 = __ldg((const float4*)(Ct + (size_t)i1.y * E) + lane);
            float4 c2 = __ldg((const float4*)(Ct + (size_t)i1.z * E) + lane);
            float4 c3 = __ldg((const float4*)(Ct + (size_t)i1.w * E) + lane);
            float4 v0 = make_float4(a0.x + a1.x + a2.x + a3.x, a0.y + a1.y + a2.y + a3.y,
                                    a0.z + a1.z + a2.z + a3.z, a0.w + a1.w + a2.w + a3.w);
            float4 v1 = make_float4(c0.x + c1.x + c2.x + c3.x, c0.y + c1.y + c2.y + c3.y,
                                    c0.z + c1.z + c2.z + c3.z, c0.w + c1.w + c2.w + c3.w);
            *((float4*)&s_emb[(lbase + i) * E] + lane)     = v0;
            *((float4*)&s_emb[(lbase + i + 1) * E] + lane) = v1;
        }
    }

    // wait for stats1, combine, weighted accumulate into g_du
    if (t == 0) { while (atomicAdd(&g_cnt[3 * B + b], 0) < BPB) { } }
    __syncthreads();
    float m1, inv1;
    combine_stats(&g_stats[1][b * BPB], lane, m1, inv1);
    {
        float4 acc = make_float4(0.f, 0.f, 0.f, 0.f);
        #pragma unroll
        for (int i = 0; i < SPW; i++) {
            float p = expf(s_logit[lbase + i] - m1) * inv1;
            float4 e = *((const float4*)&s_emb[(lbase + i) * E] + lane);
            acc.x = fmaf(p, e.x, acc.x); acc.y = fmaf(p, e.y, acc.y);
            acc.z = fmaf(p, e.z, acc.z); acc.w = fmaf(p, e.w, acc.w);
        }
        *((float4*)&sred[w][lane * 4]) = acc;
        __syncthreads();
        if (t < 128) {
            float v = sred[0][t];
            #pragma unroll
            for (int ww = 1; ww < 8; ww++) v += sred[ww][t];
            atomicAdd(&g_du[b * HH + t], v);
        }
    }
    __threadfence(); __syncthreads();
    if (t == 0) { atomicAdd(&g_cnt[4 * B + b], 1); while (atomicAdd(&g_cnt[4 * B + b], 0) < BPB) { } }
    __syncthreads();

    // ---- final: logits2 = emb2 . (h + du) -> sigmoid + length mask -> out ----
    {
        float4 du = __ldcg((const float4*)(g_du + b * HH) + lane);
        float4 u4 = make_float4(h4.x + du.x, h4.y + du.y, h4.z + du.z, h4.w + du.w);
        int len = __ldg(lengths + b);
        #pragma unroll 1
        for (int i = 0; i < SPW; i++) {
            float4 e = *((const float4*)&s_emb[(lbase + i) * E] + lane);
            float d = e.x * u4.x + e.y * u4.y + e.z * u4.z + e.w * u4.w;
            #pragma unroll
            for (int o = 16; o; o >>= 1) d += __shfl_down_sync(FULLMASK, d, o);
            if (lane == 0) {
                int sl = slot0 + w * SPW + i;
                o_mask[b * S + sl] = (sl < len) ? 1.0f / (1.0f + expf(-d)) : 0.0f;
            }
        }
    }

    final_reset(t);
}

// ---------------- host launch ----------------
extern "C" void kernel_launch(void* const* d_in, const int* in_sizes, int n_in,
                              void* d_out, int out_size)
{
    const int*   story   = (const int*)d_in[0];
    const int*   lengths = (const int*)d_in[1];
    const float* hidden  = (const float*)d_in[2];
    // d_in[3] global_pointer: unused (is_decoding == 0 path)
    const float* C       = (const float*)d_in[4];
    const float* Wm      = (const float*)d_in[5];
    const float* Wb      = (const float*)d_in[6];
    const float* W1w     = (const float*)d_in[7];
    const float* W1b     = (const float*)d_in[8];
    const float* W3w     = (const float*)d_in[9];
    const float* W3b     = (const float*)d_in[10];
    const float* W4w     = (const float*)d_in[11];
    const float* W4b     = (const float*)d_in[12];

    float* out = (float*)d_out;
    float* o_sp   = out;                       // [B,2]
    float* o_spa  = out + B * 2;               // [B,2]
    float* o_qh   = out + B * 4;               // [B,4000]
    float* o_qha  = o_qh + B * NE;             // [B,4000]
    float* o_qt   = o_qha + B * NE;            // [B,200]
    float* o_qta  = o_qt + B * NR;             // [B,200]
    float* o_mask = o_qta + B * NR;            // [B,S]

    // JAX partitionable split of key(42): k_i = threefry(key, (0, i))
    uint32_t k1a, k1b, k2a, k2b, k3a, k3b;
    threefry2x32(0u, 42u, 0u, 0u, k1a, k1b);
    threefry2x32(0u, 42u, 0u, 1u, k2a, k2b);
    threefry2x32(0u, 42u, 0u, 2u, k3a, k3b);

    const int SMEM = SPB * E * sizeof(float);  // 32KB dynamic

    // single self-resetting kernel: h + hop chain + heads + argmax
    k_mega<<<GRID, 256, SMEM>>>(
        story, C, lengths, hidden, Wm, Wb,
        W1w, W1b, W3w, W3b, W4w, W4b,
        o_sp, o_qh, o_qt, o_spa, o_qha, o_qta, o_mask,
        k1a, k1b, k2a, k2b, k3a, k3b);
}

// round 16
// speedup vs baseline: 1.5918x; 1.5918x over previous
#include <cuda_runtime.h>
#include <math.h>
#include <stdint.h>

// Problem constants
#define B 16
#define S 2048
#define M 4
#define E 128
#define HH 128
#define VOCAB 100000
#define NE 4000
#define NR 200
#define FULLMASK 0xffffffffu

// mega-kernel geometry
#define GB 512            // gather blocks (barrier participants)
#define BPB 32            // gather blocks per batch (== warp size for stats combine)
#define SPB 64            // slots per gather block
#define SPW 8             // slots per warp
#define HEADW (2 + NE + NR)               // 4202 head warps
#define HB ((HEADW * 32 + 255) / 256)     // 526 head blocks
#define AB 48                             // argmax blocks

// ---------------- device scratch (no allocation allowed) ----------------
__device__ float  g_h[B * HH];
__device__ float  g_u[B * HH];
__device__ float2 g_stats[2][B * BPB];  // per-block softmax partials (m, sum)
__device__ int    g_cnt[4 * B];         // per-batch barrier counters x 4 rounds
__device__ int    g_headcnt;            // head-block completion counter

// ---------------- threefry2x32-20 (JAX) ----------------
__host__ __device__ __forceinline__ uint32_t rotl32(uint32_t v, int d) {
    return (v << d) | (v >> (32 - d));
}

__host__ __device__ __forceinline__ void threefry2x32(
    uint32_t k0, uint32_t k1, uint32_t x0, uint32_t x1,
    uint32_t& o0, uint32_t& o1)
{
    uint32_t ks0 = k0, ks1 = k1;
    uint32_t ks2 = k0 ^ k1 ^ 0x1BD11BDAu;
    x0 += ks0; x1 += ks1;
    const int rA[4] = {13, 15, 26, 6};
    const int rB[4] = {17, 29, 16, 24};
    #pragma unroll
    for (int i = 0; i < 4; i++) { x0 += x1; x1 = rotl32(x1, rA[i]); x1 ^= x0; }
    x0 += ks1; x1 += ks2 + 1u;
    #pragma unroll
    for (int i = 0; i < 4; i++) { x0 += x1; x1 = rotl32(x1, rB[i]); x1 ^= x0; }
    x0 += ks2; x1 += ks0 + 2u;
    #pragma unroll
    for (int i = 0; i < 4; i++) { x0 += x1; x1 = rotl32(x1, rA[i]); x1 ^= x0; }
    x0 += ks0; x1 += ks1 + 3u;
    #pragma unroll
    for (int i = 0; i < 4; i++) { x0 += x1; x1 = rotl32(x1, rB[i]); x1 ^= x0; }
    x0 += ks1; x1 += ks2 + 4u;
    #pragma unroll
    for (int i = 0; i < 4; i++) { x0 += x1; x1 = rotl32(x1, rA[i]); x1 ^= x0; }
    x0 += ks2; x1 += ks0 + 5u;
    o0 = x0; o1 = x1;
}

// ---------------- h = hidden @ Wm^T + Wb ; u = h ; reset counters ----------
__global__ void k_h(const float* __restrict__ hidden,
                    const float* __restrict__ Wm,
                    const float* __restrict__ Wb)
{
    int t = threadIdx.x, lane = t & 31;
    if (blockIdx.x == 0) {
        if (t < 4 * B) g_cnt[t] = 0;
        if (t == 4 * B) g_headcnt = 0;
    }
    int gw   = blockIdx.x * 8 + (t >> 5);   // 0..2047
    int b    = gw >> 7;
    int row  = gw & 127;
    float4 wv = __ldg((const float4*)(Wm + (size_t)row * HH) + lane);
    float4 hv = __ldg((const float4*)(hidden + b * HH) + lane);
    float s = wv.x * hv.x + wv.y * hv.y + wv.z * hv.z + wv.w * hv.w;
    #pragma unroll
    for (int o = 16; o; o >>= 1) s += __shfl_down_sync(FULLMASK, s, o);
    if (lane == 0) {
        float val = s + __ldg(Wb + row);
        g_h[b * HH + row] = val;
        g_u[b * HH + row] = val;
    }
}

// butterfly-combine 32 per-block (m, sum) partials -> (m, 1/sum), all lanes
__device__ __forceinline__ void combine_stats(const float2* st_base,
                                              int lane, float& m, float& inv)
{
    float2 st = __ldcg(st_base + lane);
    float mm = st.x;
    #pragma unroll
    for (int o = 16; o; o >>= 1) mm = fmaxf(mm, __shfl_xor_sync(FULLMASK, mm, o));
    float ss = st.y * expf(st.x - mm);
    #pragma unroll
    for (int o = 16; o; o >>= 1) ss += __shfl_xor_sync(FULLMASK, ss, o);
    m = mm; inv = 1.0f / ss;
}

// ================================ MEGA KERNEL ================================
__global__ void __launch_bounds__(256, 5)
k_mega(const int* __restrict__ story,
       const float* __restrict__ C,
       const int* __restrict__ lengths,
       const float* __restrict__ W1w, const float* __restrict__ W1b,
       const float* __restrict__ W3w, const float* __restrict__ W3b,
       const float* __restrict__ W4w, const float* __restrict__ W4b,
       float* __restrict__ o_sp, float* __restrict__ o_qh, float* __restrict__ o_qt,
       float* __restrict__ a_sp, float* __restrict__ a_qh, float* __restrict__ a_qt,
       float* __restrict__ o_mask,
       uint32_t k1a, uint32_t k1b, uint32_t k2a, uint32_t k2b,
       uint32_t k3a, uint32_t k3b)
{
    extern __shared__ float s_emb[];     // SPB x E floats = 32KB (argmax: scratch)
    __shared__ float s_logit[SPB];       // 256B
    __shared__ int4  s_idx[SPB];         // 1KB: story indices, loaded once
    __shared__ float sred[8][128];       // 4KB: cross-warp u reduce

    const size_t TBL = (size_t)VOCAB * E;
    int bid = blockIdx.x;
    int t = threadIdx.x, lane = t & 31, w = t >> 5;

    // ---------------- head-GEMV blocks ----------------
    if (bid >= GB && bid < GB + HB) {
        int gid = (bid - GB) * 256 + t;
        int hw  = gid >> 5;
        if (hw < HEADW) {
            const float *W, *bias; float* outl; int N, n;
            if (hw < 2)           { W = W1w; bias = W1b; outl = o_sp; N = 2;  n = hw; }
            else if (hw < 2 + NE) { W = W3w; bias = W3b; outl = o_qh; N = NE; n = hw - 2; }
            else                  { W = W4w; bias = W4b; outl = o_qt; N = NR; n = hw - 2 - NE; }
            float4 w4 = __ldg((const float4*)(W + (size_t)n * HH) + lane);
            float  bs = __ldg(bias + n);
            #pragma unroll
            for (int b = 0; b < B; b++) {
                float4 h4 = __ldg((const float4*)(g_h + b * HH) + lane);
                float s = w4.x * h4.x + w4.y * h4.y + w4.z * h4.z + w4.w * h4.w;
                #pragma unroll
                for (int o = 16; o; o >>= 1) s += __shfl_down_sync(FULLMASK, s, o);
                if (lane == 0) outl[b * N + n] = s + bs;
            }
        }
        __threadfence();
        __syncthreads();
        if (t == 0) atomicAdd(&g_headcnt, 1);
        return;
    }

    // ---------------- argmax blocks (spin on head completion) ----------------
    if (bid >= GB + HB) {
        if (t == 0) { while (atomicAdd(&g_headcnt, 0) < HB) { __nanosleep(256); } }
        __syncthreads();
        int blk2 = bid - GB - HB;
        int head = blk2 >> 4, b = blk2 & 15;
        const float* L; float* A; int N; uint32_t ka, kb;
        if (head == 0)      { L = o_sp; A = a_sp; N = 2;  ka = k1a; kb = k1b; }
        else if (head == 1) { L = o_qh; A = a_qh; N = NE; ka = k2a; kb = k2b; }
        else                { L = o_qt; A = a_qt; N = NR; ka = k3a; kb = k3b; }

        float bv = -INFINITY; int bi = 0x7fffffff;
        for (int i = t; i < N; i += 256) {
            int idx = b * N + i;
            float logit = __ldcg(L + idx);
            uint32_t o0, o1;
            threefry2x32(ka, kb, 0u, (uint32_t)idx, o0, o1);
            uint32_t bits = o0 ^ o1;
            float u = __uint_as_float((bits >> 9) | 0x3F800000u) - 1.0f;
            float v = fmaxf(1e-10f, u + 1e-10f);
            float g = -logf(-logf(v));
            float nv = logit + g;
            if (nv > bv || (nv == bv && i < bi)) { bv = nv; bi = i; }
        }
        float* sv = s_emb;                 // carve scratch from dynamic smem
        int*   si = (int*)(s_emb + 256);
        sv[t] = bv; si[t] = bi;
        __syncthreads();
        for (int o = 128; o; o >>= 1) {
            if (t < o) {
                if (sv[t + o] > sv[t] || (sv[t + o] == sv[t] && si[t + o] < si[t])) {
                    sv[t] = sv[t + o]; si[t] = si[t + o];
                }
            }
            __syncthreads();
        }
        int best = si[0];
        float* out = A + b * N;
        for (int i = t; i < N; i += 256) out[i] = (i == best) ? 1.0f : 0.0f;
        return;
    }

    // ======================= gather blocks: full hop chain =======================
    int b     = bid / BPB;
    int blkin = bid % BPB;
    int slot0 = blkin * SPB;
    int lbase = w * SPW;
    const float* u_b = g_u + b * HH;

    // load this block's 64 story int4s once; reused by all 3 hops
    if (t < SPB) s_idx[t] = __ldg((const int4*)story + b * S + slot0 + t);
    __syncthreads();

    // ---- hop 0: gather C0, logits0 -> s_logit (fused dot, emb0 single-use) ----
    {
        float4 u4 = __ldg((const float4*)u_b + lane);   // u0 = h from prior kernel
        #pragma unroll 1
        for (int i = 0; i < SPW; i += 2) {
            int4 i0 = s_idx[lbase + i];
            int4 i1 = s_idx[lbase + i + 1];
            float4 a0 = __ldg((const float4*)(C + (size_t)i0.x * E) + lane);
            float4 a1 = __ldg((const float4*)(C + (size_t)i0.y * E) + lane);
            float4 a2 = __ldg((const float4*)(C + (size_t)i0.z * E) + lane);
            float4 a3 = __ldg((const float4*)(C + (size_t)i0.w * E) + lane);
            float4 c0 = __ldg((const float4*)(C + (size_t)i1.x * E) + lane);
            float4 c1 = __ldg((const float4*)(C + (size_t)i1.y * E) + lane);
            float4 c2 = __ldg((const float4*)(C + (size_t)i1.z * E) + lane);
            float4 c3 = __ldg((const float4*)(C + (size_t)i1.w * E) + lane);
            float sa = (a0.x + a1.x + a2.x + a3.x) * u4.x
                     + (a0.y + a1.y + a2.y + a3.y) * u4.y
                     + (a0.z + a1.z + a2.z + a3.z) * u4.z
                     + (a0.w + a1.w + a2.w + a3.w) * u4.w;
            float sb = (c0.x + c1.x + c2.x + c3.x) * u4.x
                     + (c0.y + c1.y + c2.y + c3.y) * u4.y
                     + (c0.z + c1.z + c2.z + c3.z) * u4.z
                     + (c0.w + c1.w + c2.w + c3.w) * u4.w;
            #pragma unroll
            for (int o = 16; o; o >>= 1) {
                sa += __shfl_down_sync(FULLMASK, sa, o);
                sb += __shfl_down_sync(FULLMASK, sb, o);
            }
            if (lane == 0) { s_logit[lbase + i] = sa; s_logit[lbase + i + 1] = sb; }
        }
    }
    __syncthreads();
    // stats0 partial (warp 0), then ARRIVE ONLY (no spin yet)
    if (w == 0) {
        float v0 = s_logit[lane], v1 = s_logit[lane + 32];
        float mb = fmaxf(v0, v1);
        #pragma unroll
        for (int o = 16; o; o >>= 1) mb = fmaxf(mb, __shfl_xor_sync(FULLMASK, mb, o));
        float sb = expf(v0 - mb) + expf(v1 - mb);
        #pragma unroll
        for (int o = 16; o; o >>= 1) sb += __shfl_xor_sync(FULLMASK, sb, o);
        if (lane == 0) {
            g_stats[0][b * BPB + blkin] = make_float2(mb, sb);
            __threadfence();
            atomicAdd(&g_cnt[b], 1);
        }
    }

    // ---- gather C1 -> s_emb (unweighted; overlaps the stats0 barrier) ----
    {
        const float* Ct = C + TBL;
        #pragma unroll 1
        for (int i = 0; i < SPW; i += 2) {
            int4 i0 = s_idx[lbase + i];
            int4 i1 = s_idx[lbase + i + 1];
            float4 a0 = __ldg((const float4*)(Ct + (size_t)i0.x * E) + lane);
            float4 a1 = __ldg((const float4*)(Ct + (size_t)i0.y * E) + lane);
            float4 a2 = __ldg((const float4*)(Ct + (size_t)i0.z * E) + lane);
            float4 a3 = __ldg((const float4*)(Ct + (size_t)i0.w * E) + lane);
            float4 c0 = __ldg((const float4*)(Ct + (size_t)i1.x * E) + lane);
            float4 c1 = __ldg((const float4*)(Ct + (size_t)i1.y * E) + lane);
            float4 c2 = __ldg((const float4*)(Ct + (size_t)i1.z * E) + lane);
            float4 c3 = __ldg((const float4*)(Ct + (size_t)i1.w * E) + lane);
            float4 v0 = make_float4(a0.x + a1.x + a2.x + a3.x, a0.y + a1.y + a2.y + a3.y,
                                    a0.z + a1.z + a2.z + a3.z, a0.w + a1.w + a2.w + a3.w);
            float4 v1 = make_float4(c0.x + c1.x + c2.x + c3.x, c0.y + c1.y + c2.y + c3.y,
                                    c0.z + c1.z + c2.z + c3.z, c0.w + c1.w + c2.w + c3.w);
            *((float4*)&s_emb[(lbase + i) * E] + lane)     = v0;
            *((float4*)&s_emb[(lbase + i + 1) * E] + lane) = v1;
        }
    }

    // now wait for stats0, combine, and do the cheap weighted accumulate
    if (t == 0) { while (atomicAdd(&g_cnt[b], 0) < BPB) { __nanosleep(32); } }
    __syncthreads();
    float m0, inv0;
    combine_stats(&g_stats[0][b * BPB], lane, m0, inv0);
    {
        float4 acc = make_float4(0.f, 0.f, 0.f, 0.f);
        #pragma unroll
        for (int i = 0; i < SPW; i++) {
            float p = expf(s_logit[lbase + i] - m0) * inv0;
            float4 e = *((const float4*)&s_emb[(lbase + i) * E] + lane);
            acc.x = fmaf(p, e.x, acc.x); acc.y = fmaf(p, e.y, acc.y);
            acc.z = fmaf(p, e.z, acc.z); acc.w = fmaf(p, e.w, acc.w);
        }
        *((float4*)&sred[w][lane * 4]) = acc;
        __syncthreads();
        if (t < 128) {
            float v = sred[0][t];
            #pragma unroll
            for (int ww = 1; ww < 8; ww++) v += sred[ww][t];
            atomicAdd(&g_u[b * HH + t], v);
        }
    }
    __threadfence(); __syncthreads();
    if (t == 0) { atomicAdd(&g_cnt[B + b], 1); while (atomicAdd(&g_cnt[B + b], 0) < BPB) { __nanosleep(32); } }
    __syncthreads();

    // ---- logits1 = emb1 . u1 -> s_logit (paired, interleaved shfl chains) ----
    {
        float4 u4;
        u4.x = __ldcg(g_u + b * HH + lane * 4 + 0);
        u4.y = __ldcg(g_u + b * HH + lane * 4 + 1);
        u4.z = __ldcg(g_u + b * HH + lane * 4 + 2);
        u4.w = __ldcg(g_u + b * HH + lane * 4 + 3);
        #pragma unroll 1
        for (int i = 0; i < SPW; i += 2) {
            float4 e0 = *((const float4*)&s_emb[(lbase + i) * E] + lane);
            float4 e1 = *((const float4*)&s_emb[(lbase + i + 1) * E] + lane);
            float d0 = e0.x * u4.x + e0.y * u4.y + e0.z * u4.z + e0.w * u4.w;
            float d1 = e1.x * u4.x + e1.y * u4.y + e1.z * u4.z + e1.w * u4.w;
            #pragma unroll
            for (int o = 16; o; o >>= 1) {
                d0 += __shfl_down_sync(FULLMASK, d0, o);
                d1 += __shfl_down_sync(FULLMASK, d1, o);
            }
            if (lane == 0) { s_logit[lbase + i] = d0; s_logit[lbase + i + 1] = d1; }
        }
    }
    __syncthreads();
    // stats1 partial + arrive only
    if (w == 0) {
        float v0 = s_logit[lane], v1 = s_logit[lane + 32];
        float mb = fmaxf(v0, v1);
        #pragma unroll
        for (int o = 16; o; o >>= 1) mb = fmaxf(mb, __shfl_xor_sync(FULLMASK, mb, o));
        float sb = expf(v0 - mb) + expf(v1 - mb);
        #pragma unroll
        for (int o = 16; o; o >>= 1) sb += __shfl_xor_sync(FULLMASK, sb, o);
        if (lane == 0) {
            g_stats[1][b * BPB + blkin] = make_float2(mb, sb);
            __threadfence();
            atomicAdd(&g_cnt[2 * B + b], 1);
        }
    }

    // ---- gather C2 -> s_emb (emb1 dead; overlaps the stats1 barrier) ----
    {
        const float* Ct = C + 2 * TBL;
        #pragma unroll 1
        for (int i = 0; i < SPW; i += 2) {
            int4 i0 = s_idx[lbase + i];
            int4 i1 = s_idx[lbase + i + 1];
            float4 a0 = __ldg((const float4*)(Ct + (size_t)i0.x * E) + lane);
            float4 a1 = __ldg((const float4*)(Ct + (size_t)i0.y * E) + lane);
            float4 a2 = __ldg((const float4*)(Ct + (size_t)i0.z * E) + lane);
            float4 a3 = __ldg((const float4*)(Ct + (size_t)i0.w * E) + lane);
            float4 c0 = __ldg((const float4*)(Ct + (size_t)i1.x * E) + lane);
            float4 c1 = __ldg((const float4*)(Ct + (size_t)i1.y * E) + lane);
            float4 c2 = __ldg((const float4*)(Ct + (size_t)i1.z * E) + lane);
            float4 c3 = __ldg((const float4*)(Ct + (size_t)i1.w * E) + lane);
            float4 v0 = make_float4(a0.x + a1.x + a2.x + a3.x, a0.y + a1.y + a2.y + a3.y,
                                    a0.z + a1.z + a2.z + a3.z, a0.w + a1.w + a2.w + a3.w);
            float4 v1 = make_float4(c0.x + c1.x + c2.x + c3.x, c0.y + c1.y + c2.y + c3.y,
                                    c0.z + c1.z + c2.z + c3.z, c0.w + c1.w + c2.w + c3.w);
            *((float4*)&s_emb[(lbase + i) * E] + lane)     = v0;
            *((float4*)&s_emb[(lbase + i + 1) * E] + lane) = v1;
        }
    }

    // wait for stats1, combine, weighted accumulate into u
    if (t == 0) { while (atomicAdd(&g_cnt[2 * B + b], 0) < BPB) { __nanosleep(32); } }
    __syncthreads();
    float m1, inv1;
    combine_stats(&g_stats[1][b * BPB], lane, m1, inv1);
    {
        float4 acc = make_float4(0.f, 0.f, 0.f, 0.f);
        #pragma unroll
        for (int i = 0; i < SPW; i++) {
            float p = expf(s_logit[lbase + i] - m1) * inv1;
            float4 e = *((const float4*)&s_emb[(lbase + i) * E] + lane);
            acc.x = fmaf(p, e.x, acc.x); acc.y = fmaf(p, e.y, acc.y);
            acc.z = fmaf(p, e.z, acc.z); acc.w = fmaf(p, e.w, acc.w);
        }
        *((float4*)&sred[w][lane * 4]) = acc;
        __syncthreads();
        if (t < 128) {
            float v = sred[0][t];
            #pragma unroll
            for (int ww = 1; ww < 8; ww++) v += sred[ww][t];
            atomicAdd(&g_u[b * HH + t], v);
        }
    }
    __threadfence(); __syncthreads();
    if (t == 0) { atomicAdd(&g_cnt[3 * B + b], 1); while (atomicAdd(&g_cnt[3 * B + b], 0) < BPB) { __nanosleep(32); } }
    __syncthreads();

    // ---- final: logits2 = emb2 . u2 -> sigmoid + mask (paired chains) ----
    {
        float4 u4;
        u4.x = __ldcg(g_u + b * HH + lane * 4 + 0);
        u4.y = __ldcg(g_u + b * HH + lane * 4 + 1);
        u4.z = __ldcg(g_u + b * HH + lane * 4 + 2);
        u4.w = __ldcg(g_u + b * HH + lane * 4 + 3);
        int len = __ldg(lengths + b);
        #pragma unroll 1
        for (int i = 0; i < SPW; i += 2) {
            float4 e0 = *((const float4*)&s_emb[(lbase + i) * E] + lane);
            float4 e1 = *((const float4*)&s_emb[(lbase + i + 1) * E] + lane);
            float d0 = e0.x * u4.x + e0.y * u4.y + e0.z * u4.z + e0.w * u4.w;
            float d1 = e1.x * u4.x + e1.y * u4.y + e1.z * u4.z + e1.w * u4.w;
            #pragma unroll
            for (int o = 16; o; o >>= 1) {
                d0 += __shfl_down_sync(FULLMASK, d0, o);
                d1 += __shfl_down_sync(FULLMASK, d1, o);
            }
            if (lane == 0) {
                int sl = slot0 + w * SPW + i;
                o_mask[b * S + sl]     = (sl < len)     ? 1.0f / (1.0f + expf(-d0)) : 0.0f;
                o_mask[b * S + sl + 1] = (sl + 1 < len) ? 1.0f / (1.0f + expf(-d1)) : 0.0f;
            }
        }
    }
}

// ---------------- host launch ----------------
extern "C" void kernel_launch(void* const* d_in, const int* in_sizes, int n_in,
                              void* d_out, int out_size)
{
    const int*   story   = (const int*)d_in[0];
    const int*   lengths = (const int*)d_in[1];
    const float* hidden  = (const float*)d_in[2];
    // d_in[3] global_pointer: unused (is_decoding == 0 path)
    const float* C       = (const float*)d_in[4];
    const float* Wm      = (const float*)d_in[5];
    const float* Wb      = (const float*)d_in[6];
    const float* W1w     = (const float*)d_in[7];
    const float* W1b     = (const float*)d_in[8];
    const float* W3w     = (const float*)d_in[9];
    const float* W3b     = (const float*)d_in[10];
    const float* W4w     = (const float*)d_in[11];
    const float* W4b     = (const float*)d_in[12];

    float* out = (float*)d_out;
    float* o_sp   = out;                       // [B,2]
    float* o_spa  = out + B * 2;               // [B,2]
    float* o_qh   = out + B * 4;               // [B,4000]
    float* o_qha  = o_qh + B * NE;             // [B,4000]
    float* o_qt   = o_qha + B * NE;            // [B,200]
    float* o_qta  = o_qt + B * NR;             // [B,200]
    float* o_mask = o_qta + B * NR;            // [B,S]

    // JAX partitionable split of key(42): k_i = threefry(key, (0, i))
    uint32_t k1a, k1b, k2a, k2b, k3a, k3b;
    threefry2x32(0u, 42u, 0u, 0u, k1a, k1b);
    threefry2x32(0u, 42u, 0u, 1u, k2a, k2b);
    threefry2x32(0u, 42u, 0u, 2u, k3a, k3b);

    const int SMEM = SPB * E * sizeof(float);  // 32KB dynamic

    // 1) h = hidden@Wm^T + b ; u = h ; reset counters
    k_h<<<256, 256>>>(hidden, Wm, Wb);

    // 2) hop chain (512 barrier blocks) + heads + argmax
    k_mega<<<GB + HB + AB, 256, SMEM>>>(
        story, C, lengths,
        W1w, W1b, W3w, W3b, W4w, W4b,
        o_sp, o_qh, o_qt, o_spa, o_qha, o_qta, o_mask,
        k1a, k1b, k2a, k2b, k3a, k3b);
}